// round 8
// baseline (speedup 1.0000x reference)
#include <cuda_runtime.h>
#include <cuda_fp16.h>
#include <cstdint>

#define N_NODES 100000
#define N_EDGES 1600000
#define DIM 128

#define SCAN_CHUNK 1024
#define NB_SCAN ((N_NODES + SCAN_CHUNK - 1) / SCAN_CHUNK)  // 98

// -------- device scratch (no cudaMalloc allowed) --------
__device__ int    g_is64;
__device__ int    g_degi[N_NODES];
__device__ int    g_start[N_NODES];
__device__ int    g_cursor[N_NODES];
__device__ int    g_csr[N_EDGES];
__device__ int    g_bsum[128];
__device__ int    g_boff[128];
__device__ float  g_dis[N_NODES];
__device__ float  g_xs[(size_t)N_NODES * DIM];   // x @ W, fp32 (GEMM out)
__device__ __half g_xsh[(size_t)N_NODES * DIM];  // dis[n] * (x @ W)[n], fp16

// ================= helpers =================

__device__ __forceinline__ uint32_t f2tf32_bits(float a) {
    uint32_t u;
    asm("cvt.rna.tf32.f32 %0, %1;" : "=r"(u) : "f"(a));
    return u;
}

#define MMA_TF32(d, a, b)                                                     \
    asm volatile("mma.sync.aligned.m16n8k8.row.col.f32.tf32.tf32.f32 "        \
                 "{%0,%1,%2,%3}, {%4,%5,%6,%7}, {%8,%9}, {%0,%1,%2,%3};"      \
                 : "+f"((d)[0]), "+f"((d)[1]), "+f"((d)[2]), "+f"((d)[3])     \
                 : "r"((a)[0]), "r"((a)[1]), "r"((a)[2]), "r"((a)[3]),        \
                   "r"((b)[0]), "r"((b)[1]))

// ================= init: zero degree + dtype detect =================

__global__ void k_init(const void* __restrict__ ei) {
    int i = blockIdx.x * blockDim.x + threadIdx.x;
    if (i < N_NODES) g_degi[i] = 0;
    if (blockIdx.x == 0) {
        const long long* p = (const long long*)ei;
        __shared__ int bad;
        if (threadIdx.x == 0) bad = 0;
        __syncthreads();
        for (int j = threadIdx.x; j < 2048; j += blockDim.x) {
            long long v = p[j];
            if (v < 0 || v >= N_NODES) bad = 1;
        }
        __syncthreads();
        if (threadIdx.x == 0) g_is64 = bad ? 0 : 1;
    }
}

// ================= degree histogram =================

__global__ void k_hist(const void* __restrict__ ei) {
    int e2 = blockIdx.x * blockDim.x + threadIdx.x;
    if (e2 >= N_EDGES / 2) return;
    int d0, d1;
    if (g_is64) {
        const longlong2* p = (const longlong2*)ei;
        longlong2 d = p[N_EDGES / 2 + e2];
        d0 = (int)d.x; d1 = (int)d.y;
    } else {
        const int2* p = (const int2*)ei;
        int2 d = p[N_EDGES / 2 + e2];
        d0 = d.x; d1 = d.y;
    }
    atomicAdd(&g_degi[d0], 1);
    atomicAdd(&g_degi[d1], 1);
}

// ================= 3-pass scan =================

__global__ void __launch_bounds__(256) k_scanA() {
    int base = blockIdx.x * SCAN_CHUNK;
    int idx = base + threadIdx.x * 4;
    int lane = threadIdx.x & 31, wid = threadIdx.x >> 5;
    int s = 0;
#pragma unroll
    for (int j = 0; j < 4; j++)
        if (idx + j < N_NODES) s += g_degi[idx + j];
#pragma unroll
    for (int o = 16; o > 0; o >>= 1) s += __shfl_down_sync(0xffffffffu, s, o);
    __shared__ int ws[8];
    if (lane == 0) ws[wid] = s;
    __syncthreads();
    if (threadIdx.x == 0) {
        int t = 0;
#pragma unroll
        for (int w = 0; w < 8; w++) t += ws[w];
        g_bsum[blockIdx.x] = t;
    }
}

__global__ void __launch_bounds__(128) k_scanB() {
    int tid = threadIdx.x;
    int lane = tid & 31, wid = tid >> 5;
    int v = (tid < NB_SCAN) ? g_bsum[tid] : 0;
    int iv = v;
#pragma unroll
    for (int o = 1; o < 32; o <<= 1) {
        int u = __shfl_up_sync(0xffffffffu, iv, o);
        if (lane >= o) iv += u;
    }
    __shared__ int wt[4];
    if (lane == 31) wt[wid] = iv;
    __syncthreads();
    if (tid == 0) {
        int a = wt[0], b = wt[1], c = wt[2];
        wt[1] = a; wt[2] = a + b; wt[3] = a + b + c; wt[0] = 0;
    }
    __syncthreads();
    g_boff[tid] = wt[wid] + iv - v;
}

__global__ void __launch_bounds__(256) k_scanC() {
    int base = blockIdx.x * SCAN_CHUNK;
    int idx = base + threadIdx.x * 4;
    int lane = threadIdx.x & 31, wid = threadIdx.x >> 5;
    int v[4];
#pragma unroll
    for (int j = 0; j < 4; j++)
        v[j] = (idx + j < N_NODES) ? g_degi[idx + j] : 0;
    int s0 = v[0], s1 = s0 + v[1], s2 = s1 + v[2], s3 = s2 + v[3];
    int t = s3;
#pragma unroll
    for (int o = 1; o < 32; o <<= 1) {
        int u = __shfl_up_sync(0xffffffffu, t, o);
        if (lane >= o) t += u;
    }
    __shared__ int ws[8];
    if (lane == 31) ws[wid] = t;
    __syncthreads();
    if (threadIdx.x == 0) {
        int acc = 0;
#pragma unroll
        for (int w = 0; w < 8; w++) { int x = ws[w]; ws[w] = acc; acc += x; }
    }
    __syncthreads();
    int excl = g_boff[blockIdx.x] + ws[wid] + (t - s3);
    int e[4] = {excl, excl + s0, excl + s1, excl + s2};
#pragma unroll
    for (int j = 0; j < 4; j++) {
        if (idx + j < N_NODES) {
            g_start[idx + j]  = e[j];
            g_cursor[idx + j] = e[j];
            g_dis[idx + j]    = rsqrtf((float)(v[j] + 1));
        }
    }
}

// ================= CSR fill =================

__global__ void k_fill(const void* __restrict__ ei) {
    int e2 = blockIdx.x * blockDim.x + threadIdx.x;
    if (e2 >= N_EDGES / 2) return;
    int s0, s1, d0, d1;
    if (g_is64) {
        const longlong2* p = (const longlong2*)ei;
        longlong2 s = p[e2];
        longlong2 d = p[N_EDGES / 2 + e2];
        s0 = (int)s.x; s1 = (int)s.y; d0 = (int)d.x; d1 = (int)d.y;
    } else {
        const int2* p = (const int2*)ei;
        int2 s = p[e2];
        int2 d = p[N_EDGES / 2 + e2];
        s0 = s.x; s1 = s.y; d0 = d.x; d1 = d.y;
    }
    int p0 = atomicAdd(&g_cursor[d0], 1);
    g_csr[p0] = s0;
    int p1 = atomicAdd(&g_cursor[d1], 1);
    g_csr[p1] = s1;
}

// ================= GEMM via mma.sync tf32 (3-pass split), fp32 out ==========

#define KC 16
#define A_STR 20
#define B_STR 132

__global__ void __launch_bounds__(256) k_gemm_mma(const float* __restrict__ x,
                                                  const float* __restrict__ W) {
    __shared__ uint32_t Ah[128][A_STR];
    __shared__ uint32_t Al[128][A_STR];
    __shared__ uint32_t Bh[KC][B_STR];
    __shared__ uint32_t Bl[KC][B_STR];

    int tid = threadIdx.x;
    int wid = tid >> 5, lane = tid & 31;
    int g = lane >> 2, t = lane & 3;
    int wr = wid >> 2, wc = wid & 3;
    int row0 = blockIdx.x * 128;

    float acc[4][4][4];
#pragma unroll
    for (int mt = 0; mt < 4; mt++)
#pragma unroll
        for (int nt = 0; nt < 4; nt++)
#pragma unroll
            for (int q = 0; q < 4; q++) acc[mt][nt][q] = 0.f;

    for (int k0 = 0; k0 < 128; k0 += KC) {
        __syncthreads();
#pragma unroll
        for (int i = 0; i < 2; i++) {
            int idx = tid + i * 256;
            int r = idx >> 2, c4 = idx & 3;
            int gr = row0 + r;
            float4 v = make_float4(0.f, 0.f, 0.f, 0.f);
            if (gr < N_NODES) v = ((const float4*)x)[(size_t)gr * 32 + (k0 >> 2) + c4];
            uint32_t hx = f2tf32_bits(v.x), hy = f2tf32_bits(v.y);
            uint32_t hz = f2tf32_bits(v.z), hw = f2tf32_bits(v.w);
            Ah[r][c4 * 4 + 0] = hx; Ah[r][c4 * 4 + 1] = hy;
            Ah[r][c4 * 4 + 2] = hz; Ah[r][c4 * 4 + 3] = hw;
            Al[r][c4 * 4 + 0] = f2tf32_bits(v.x - __uint_as_float(hx));
            Al[r][c4 * 4 + 1] = f2tf32_bits(v.y - __uint_as_float(hy));
            Al[r][c4 * 4 + 2] = f2tf32_bits(v.z - __uint_as_float(hz));
            Al[r][c4 * 4 + 3] = f2tf32_bits(v.w - __uint_as_float(hw));
        }
#pragma unroll
        for (int i = 0; i < 2; i++) {
            int idx = tid + i * 256;
            int r = idx >> 5, c4 = idx & 31;
            float4 v = ((const float4*)W)[(size_t)(k0 + r) * 32 + c4];
            uint32_t hx = f2tf32_bits(v.x), hy = f2tf32_bits(v.y);
            uint32_t hz = f2tf32_bits(v.z), hw = f2tf32_bits(v.w);
            Bh[r][c4 * 4 + 0] = hx; Bh[r][c4 * 4 + 1] = hy;
            Bh[r][c4 * 4 + 2] = hz; Bh[r][c4 * 4 + 3] = hw;
            Bl[r][c4 * 4 + 0] = f2tf32_bits(v.x - __uint_as_float(hx));
            Bl[r][c4 * 4 + 1] = f2tf32_bits(v.y - __uint_as_float(hy));
            Bl[r][c4 * 4 + 2] = f2tf32_bits(v.z - __uint_as_float(hz));
            Bl[r][c4 * 4 + 3] = f2tf32_bits(v.w - __uint_as_float(hw));
        }
        __syncthreads();

#pragma unroll
        for (int kt = 0; kt < KC / 8; kt++) {
            int kb = kt * 8;
            uint32_t ah[4][4], al[4][4];
#pragma unroll
            for (int mt = 0; mt < 4; mt++) {
                int r0 = wr * 64 + mt * 16;
                ah[mt][0] = Ah[r0 + g][kb + t];
                ah[mt][1] = Ah[r0 + g + 8][kb + t];
                ah[mt][2] = Ah[r0 + g][kb + t + 4];
                ah[mt][3] = Ah[r0 + g + 8][kb + t + 4];
                al[mt][0] = Al[r0 + g][kb + t];
                al[mt][1] = Al[r0 + g + 8][kb + t];
                al[mt][2] = Al[r0 + g][kb + t + 4];
                al[mt][3] = Al[r0 + g + 8][kb + t + 4];
            }
            uint32_t bh[4][2], bl[4][2];
#pragma unroll
            for (int nt = 0; nt < 4; nt++) {
                int c0 = wc * 32 + nt * 8;
                bh[nt][0] = Bh[kb + t][c0 + g];
                bh[nt][1] = Bh[kb + t + 4][c0 + g];
                bl[nt][0] = Bl[kb + t][c0 + g];
                bl[nt][1] = Bl[kb + t + 4][c0 + g];
            }
#pragma unroll
            for (int mt = 0; mt < 4; mt++)
#pragma unroll
                for (int nt = 0; nt < 4; nt++) {
                    MMA_TF32(acc[mt][nt], ah[mt], bh[nt]);
                    MMA_TF32(acc[mt][nt], ah[mt], bl[nt]);
                    MMA_TF32(acc[mt][nt], al[mt], bh[nt]);
                }
        }
    }

#pragma unroll
    for (int mt = 0; mt < 4; mt++) {
        int ra = row0 + wr * 64 + mt * 16 + g;
        int rb = ra + 8;
#pragma unroll
        for (int nt = 0; nt < 4; nt++) {
            int col = wc * 32 + nt * 8 + 2 * t;
            if (ra < N_NODES) {
                float2 v = make_float2(acc[mt][nt][0], acc[mt][nt][1]);
                *(float2*)&g_xs[(size_t)ra * DIM + col] = v;
            }
            if (rb < N_NODES) {
                float2 v = make_float2(acc[mt][nt][2], acc[mt][nt][3]);
                *(float2*)&g_xs[(size_t)rb * DIM + col] = v;
            }
        }
    }
}

// ================= scale: g_xsh[n] = fp16(dis[n] * g_xs[n]) =================
// One uint4 (8 halves) per thread. Needs GEMM + scanC done.

__global__ void __launch_bounds__(256) k_scale() {
    int idx = blockIdx.x * blockDim.x + threadIdx.x;  // uint4 index, 16/row
    if (idx >= N_NODES * 16) return;
    int n = idx >> 4;
    float dn = g_dis[n];
    const float4* src = (const float4*)g_xs;
    float4 a = src[(size_t)idx * 2];
    float4 b = src[(size_t)idx * 2 + 1];
    __half2 h0 = __floats2half2_rn(a.x * dn, a.y * dn);
    __half2 h1 = __floats2half2_rn(a.z * dn, a.w * dn);
    __half2 h2 = __floats2half2_rn(b.x * dn, b.y * dn);
    __half2 h3 = __floats2half2_rn(b.z * dn, b.w * dn);
    uint4 o;
    o.x = *(uint32_t*)&h0; o.y = *(uint32_t*)&h1;
    o.z = *(uint32_t*)&h2; o.w = *(uint32_t*)&h3;
    ((uint4*)g_xsh)[idx] = o;
}

// ================= aggregate: half-warp per node =================
// out[n] = dis[n] * (xsh[n] + sum_{s in row n} xsh[s])   (xsh pre-scaled)
// 16 lanes per node, each lane covers 8 cols via one uint4 (16B) gather.

__device__ __forceinline__ void add8(float* a, uint4 v) {
    __half2* h = (__half2*)&v;
#pragma unroll
    for (int i = 0; i < 4; i++) {
        float2 f = __half22float2(h[i]);
        a[2 * i]     += f.x;
        a[2 * i + 1] += f.y;
    }
}

__global__ void __launch_bounds__(256) k_agg(float* __restrict__ out) {
    int tid = blockIdx.x * blockDim.x + threadIdx.x;
    int n = tid >> 4;               // half-warp per node
    int l16 = threadIdx.x & 15;
    if (n >= N_NODES) return;

    int e   = g_start[n];
    int end = g_cursor[n];
    float dn = g_dis[n];

    const uint4* xs = (const uint4*)g_xsh;  // 16 uint4 per row

    float a0[8] = {0, 0, 0, 0, 0, 0, 0, 0};
    float a1[8] = {0, 0, 0, 0, 0, 0, 0, 0};
    add8(a0, xs[(size_t)n * 16 + l16]);     // self (pre-scaled by dn)

    while (e + 1 < end) {
        int s0 = g_csr[e];
        int s1 = g_csr[e + 1];
        uint4 v0 = xs[(size_t)s0 * 16 + l16];
        uint4 v1 = xs[(size_t)s1 * 16 + l16];
        add8(a0, v0);
        add8(a1, v1);
        e += 2;
    }
    if (e < end) {
        int s0 = g_csr[e];
        add8(a0, xs[(size_t)s0 * 16 + l16]);
    }

    float4 o0, o1;
    o0.x = (a0[0] + a1[0]) * dn; o0.y = (a0[1] + a1[1]) * dn;
    o0.z = (a0[2] + a1[2]) * dn; o0.w = (a0[3] + a1[3]) * dn;
    o1.x = (a0[4] + a1[4]) * dn; o1.y = (a0[5] + a1[5]) * dn;
    o1.z = (a0[6] + a1[6]) * dn; o1.w = (a0[7] + a1[7]) * dn;
    float4* op = (float4*)out + (size_t)n * 32 + l16 * 2;
    op[0] = o0;
    op[1] = o1;
}

// ================= side stream ctx =================

struct SideCtx {
    cudaStream_t s;
    cudaEvent_t ef, ec, ej;
    bool ok;
    SideCtx() : s(0), ef(0), ec(0), ej(0), ok(false) {
        if (cudaStreamCreateWithFlags(&s, cudaStreamNonBlocking) != cudaSuccess) return;
        if (cudaEventCreateWithFlags(&ef, cudaEventDisableTiming) != cudaSuccess) return;
        if (cudaEventCreateWithFlags(&ec, cudaEventDisableTiming) != cudaSuccess) return;
        if (cudaEventCreateWithFlags(&ej, cudaEventDisableTiming) != cudaSuccess) return;
        ok = true;
    }
};
static SideCtx g_side;

// ================= launch =================

extern "C" void kernel_launch(void* const* d_in, const int* in_sizes, int n_in,
                              void* d_out, int out_size) {
    const float* x = 0;
    const float* W = 0;
    const void* ei = 0;
    for (int i = 0; i < n_in; i++) {
        if (in_sizes[i] == 2 * N_EDGES)        ei = d_in[i];
        else if (in_sizes[i] == DIM * DIM)     W  = (const float*)d_in[i];
        else if (in_sizes[i] == N_NODES * DIM) x  = (const float*)d_in[i];
    }
    float* out = (float*)d_out;

    int gemm_grid = (N_NODES + 127) / 128;
    int scale_grid = (N_NODES * 16 + 255) / 256;
    bool forked = g_side.ok;

    if (forked) {
        // side: GEMM starts immediately
        cudaEventRecord(g_side.ef, 0);
        cudaStreamWaitEvent(g_side.s, g_side.ef, 0);
        k_gemm_mma<<<gemm_grid, 256, 0, g_side.s>>>(x, W);
    }

    k_init<<<(N_NODES + 255) / 256, 256>>>(ei);
    k_hist<<<(N_EDGES / 2 + 255) / 256, 256>>>(ei);
    k_scanA<<<NB_SCAN, 256>>>();
    k_scanB<<<1, 128>>>();
    k_scanC<<<NB_SCAN, 256>>>();

    if (forked) {
        // scale needs scanC (dis) + GEMM; runs concurrent with fill
        cudaEventRecord(g_side.ec, 0);
        cudaStreamWaitEvent(g_side.s, g_side.ec, 0);
        k_scale<<<scale_grid, 256, 0, g_side.s>>>();
        cudaEventRecord(g_side.ej, g_side.s);
    }

    k_fill<<<(N_EDGES / 2 + 255) / 256, 256>>>(ei);

    if (forked) {
        cudaStreamWaitEvent(0, g_side.ej, 0);
    } else {
        k_gemm_mma<<<gemm_grid, 256>>>(x, W);
        k_scale<<<scale_grid, 256>>>();
    }

    long long total = (long long)N_NODES * 16;
    k_agg<<<(int)((total + 255) / 256), 256>>>(out);
}

// round 9
// speedup vs baseline: 1.1452x; 1.1452x over previous
#include <cuda_runtime.h>
#include <cuda_fp16.h>
#include <cstdint>

#define N_NODES 100000
#define N_EDGES 1600000
#define DIM 128

#define SCAN_CHUNK 1024
#define NB_SCAN ((N_NODES + SCAN_CHUNK - 1) / SCAN_CHUNK)  // 98

// -------- device scratch (no cudaMalloc allowed) --------
__device__ int    g_is64;
__device__ int    g_degi[N_NODES];
__device__ int    g_start[N_NODES];
__device__ int    g_cursor[N_NODES];
__device__ int    g_csr[N_EDGES];
__device__ int    g_bsum[128];
__device__ int    g_boff[128];
__device__ float  g_dis[N_NODES];
__device__ __half g_xsh[(size_t)N_NODES * DIM];  // x @ W, fp16

// ================= helpers =================

__device__ __forceinline__ uint32_t f2tf32_bits(float a) {
    uint32_t u;
    asm("cvt.rna.tf32.f32 %0, %1;" : "=r"(u) : "f"(a));
    return u;
}

#define MMA_TF32(d, a, b)                                                     \
    asm volatile("mma.sync.aligned.m16n8k8.row.col.f32.tf32.tf32.f32 "        \
                 "{%0,%1,%2,%3}, {%4,%5,%6,%7}, {%8,%9}, {%0,%1,%2,%3};"      \
                 : "+f"((d)[0]), "+f"((d)[1]), "+f"((d)[2]), "+f"((d)[3])     \
                 : "r"((a)[0]), "r"((a)[1]), "r"((a)[2]), "r"((a)[3]),        \
                   "r"((b)[0]), "r"((b)[1]))

// ================= init: zero degree + dtype detect =================

__global__ void k_init(const void* __restrict__ ei) {
    int i = blockIdx.x * blockDim.x + threadIdx.x;
    if (i < N_NODES) g_degi[i] = 0;
    if (blockIdx.x == 0) {
        const long long* p = (const long long*)ei;
        __shared__ int bad;
        if (threadIdx.x == 0) bad = 0;
        __syncthreads();
        for (int j = threadIdx.x; j < 2048; j += blockDim.x) {
            long long v = p[j];
            if (v < 0 || v >= N_NODES) bad = 1;
        }
        __syncthreads();
        if (threadIdx.x == 0) g_is64 = bad ? 0 : 1;
    }
}

// ================= degree histogram =================

__global__ void k_hist(const void* __restrict__ ei) {
    int e2 = blockIdx.x * blockDim.x + threadIdx.x;
    if (e2 >= N_EDGES / 2) return;
    int d0, d1;
    if (g_is64) {
        const longlong2* p = (const longlong2*)ei;
        longlong2 d = p[N_EDGES / 2 + e2];
        d0 = (int)d.x; d1 = (int)d.y;
    } else {
        const int2* p = (const int2*)ei;
        int2 d = p[N_EDGES / 2 + e2];
        d0 = d.x; d1 = d.y;
    }
    atomicAdd(&g_degi[d0], 1);
    atomicAdd(&g_degi[d1], 1);
}

// ================= 3-pass scan =================

__global__ void __launch_bounds__(256) k_scanA() {
    int base = blockIdx.x * SCAN_CHUNK;
    int idx = base + threadIdx.x * 4;
    int lane = threadIdx.x & 31, wid = threadIdx.x >> 5;
    int s = 0;
#pragma unroll
    for (int j = 0; j < 4; j++)
        if (idx + j < N_NODES) s += g_degi[idx + j];
#pragma unroll
    for (int o = 16; o > 0; o >>= 1) s += __shfl_down_sync(0xffffffffu, s, o);
    __shared__ int ws[8];
    if (lane == 0) ws[wid] = s;
    __syncthreads();
    if (threadIdx.x == 0) {
        int t = 0;
#pragma unroll
        for (int w = 0; w < 8; w++) t += ws[w];
        g_bsum[blockIdx.x] = t;
    }
}

__global__ void __launch_bounds__(128) k_scanB() {
    int tid = threadIdx.x;
    int lane = tid & 31, wid = tid >> 5;
    int v = (tid < NB_SCAN) ? g_bsum[tid] : 0;
    int iv = v;
#pragma unroll
    for (int o = 1; o < 32; o <<= 1) {
        int u = __shfl_up_sync(0xffffffffu, iv, o);
        if (lane >= o) iv += u;
    }
    __shared__ int wt[4];
    if (lane == 31) wt[wid] = iv;
    __syncthreads();
    if (tid == 0) {
        int a = wt[0], b = wt[1], c = wt[2];
        wt[1] = a; wt[2] = a + b; wt[3] = a + b + c; wt[0] = 0;
    }
    __syncthreads();
    g_boff[tid] = wt[wid] + iv - v;
}

__global__ void __launch_bounds__(256) k_scanC() {
    int base = blockIdx.x * SCAN_CHUNK;
    int idx = base + threadIdx.x * 4;
    int lane = threadIdx.x & 31, wid = threadIdx.x >> 5;
    int v[4];
#pragma unroll
    for (int j = 0; j < 4; j++)
        v[j] = (idx + j < N_NODES) ? g_degi[idx + j] : 0;
    int s0 = v[0], s1 = s0 + v[1], s2 = s1 + v[2], s3 = s2 + v[3];
    int t = s3;
#pragma unroll
    for (int o = 1; o < 32; o <<= 1) {
        int u = __shfl_up_sync(0xffffffffu, t, o);
        if (lane >= o) t += u;
    }
    __shared__ int ws[8];
    if (lane == 31) ws[wid] = t;
    __syncthreads();
    if (threadIdx.x == 0) {
        int acc = 0;
#pragma unroll
        for (int w = 0; w < 8; w++) { int x = ws[w]; ws[w] = acc; acc += x; }
    }
    __syncthreads();
    int excl = g_boff[blockIdx.x] + ws[wid] + (t - s3);
    int e[4] = {excl, excl + s0, excl + s1, excl + s2};
#pragma unroll
    for (int j = 0; j < 4; j++) {
        if (idx + j < N_NODES) {
            g_start[idx + j]  = e[j];
            g_cursor[idx + j] = e[j];
            g_dis[idx + j]    = rsqrtf((float)(v[j] + 1));
        }
    }
}

// ================= CSR fill =================

__global__ void k_fill(const void* __restrict__ ei) {
    int e2 = blockIdx.x * blockDim.x + threadIdx.x;
    if (e2 >= N_EDGES / 2) return;
    int s0, s1, d0, d1;
    if (g_is64) {
        const longlong2* p = (const longlong2*)ei;
        longlong2 s = p[e2];
        longlong2 d = p[N_EDGES / 2 + e2];
        s0 = (int)s.x; s1 = (int)s.y; d0 = (int)d.x; d1 = (int)d.y;
    } else {
        const int2* p = (const int2*)ei;
        int2 s = p[e2];
        int2 d = p[N_EDGES / 2 + e2];
        s0 = s.x; s1 = s.y; d0 = d.x; d1 = d.y;
    }
    int p0 = atomicAdd(&g_cursor[d0], 1);
    g_csr[p0] = s0;
    int p1 = atomicAdd(&g_cursor[d1], 1);
    g_csr[p1] = s1;
}

// ================= GEMM via mma.sync tf32 (3-pass split), fp16 out ==========
// CTA: 128 rows x 128 cols, 256 threads (8 warps), warp tile 64x32.

#define KC 16
#define A_STR 20
#define B_STR 132

__global__ void __launch_bounds__(256) k_gemm_mma(const float* __restrict__ x,
                                                  const float* __restrict__ W) {
    __shared__ uint32_t Ah[128][A_STR];
    __shared__ uint32_t Al[128][A_STR];
    __shared__ uint32_t Bh[KC][B_STR];
    __shared__ uint32_t Bl[KC][B_STR];

    int tid = threadIdx.x;
    int wid = tid >> 5, lane = tid & 31;
    int g = lane >> 2, t = lane & 3;
    int wr = wid >> 2, wc = wid & 3;
    int row0 = blockIdx.x * 128;

    float acc[4][4][4];
#pragma unroll
    for (int mt = 0; mt < 4; mt++)
#pragma unroll
        for (int nt = 0; nt < 4; nt++)
#pragma unroll
            for (int q = 0; q < 4; q++) acc[mt][nt][q] = 0.f;

    for (int k0 = 0; k0 < 128; k0 += KC) {
        __syncthreads();
#pragma unroll
        for (int i = 0; i < 2; i++) {
            int idx = tid + i * 256;
            int r = idx >> 2, c4 = idx & 3;
            int gr = row0 + r;
            float4 v = make_float4(0.f, 0.f, 0.f, 0.f);
            if (gr < N_NODES) v = ((const float4*)x)[(size_t)gr * 32 + (k0 >> 2) + c4];
            uint32_t hx = f2tf32_bits(v.x), hy = f2tf32_bits(v.y);
            uint32_t hz = f2tf32_bits(v.z), hw = f2tf32_bits(v.w);
            Ah[r][c4 * 4 + 0] = hx; Ah[r][c4 * 4 + 1] = hy;
            Ah[r][c4 * 4 + 2] = hz; Ah[r][c4 * 4 + 3] = hw;
            Al[r][c4 * 4 + 0] = f2tf32_bits(v.x - __uint_as_float(hx));
            Al[r][c4 * 4 + 1] = f2tf32_bits(v.y - __uint_as_float(hy));
            Al[r][c4 * 4 + 2] = f2tf32_bits(v.z - __uint_as_float(hz));
            Al[r][c4 * 4 + 3] = f2tf32_bits(v.w - __uint_as_float(hw));
        }
#pragma unroll
        for (int i = 0; i < 2; i++) {
            int idx = tid + i * 256;
            int r = idx >> 5, c4 = idx & 31;
            float4 v = ((const float4*)W)[(size_t)(k0 + r) * 32 + c4];
            uint32_t hx = f2tf32_bits(v.x), hy = f2tf32_bits(v.y);
            uint32_t hz = f2tf32_bits(v.z), hw = f2tf32_bits(v.w);
            Bh[r][c4 * 4 + 0] = hx; Bh[r][c4 * 4 + 1] = hy;
            Bh[r][c4 * 4 + 2] = hz; Bh[r][c4 * 4 + 3] = hw;
            Bl[r][c4 * 4 + 0] = f2tf32_bits(v.x - __uint_as_float(hx));
            Bl[r][c4 * 4 + 1] = f2tf32_bits(v.y - __uint_as_float(hy));
            Bl[r][c4 * 4 + 2] = f2tf32_bits(v.z - __uint_as_float(hz));
            Bl[r][c4 * 4 + 3] = f2tf32_bits(v.w - __uint_as_float(hw));
        }
        __syncthreads();

#pragma unroll
        for (int kt = 0; kt < KC / 8; kt++) {
            int kb = kt * 8;
            uint32_t ah[4][4], al[4][4];
#pragma unroll
            for (int mt = 0; mt < 4; mt++) {
                int r0 = wr * 64 + mt * 16;
                ah[mt][0] = Ah[r0 + g][kb + t];
                ah[mt][1] = Ah[r0 + g + 8][kb + t];
                ah[mt][2] = Ah[r0 + g][kb + t + 4];
                ah[mt][3] = Ah[r0 + g + 8][kb + t + 4];
                al[mt][0] = Al[r0 + g][kb + t];
                al[mt][1] = Al[r0 + g + 8][kb + t];
                al[mt][2] = Al[r0 + g][kb + t + 4];
                al[mt][3] = Al[r0 + g + 8][kb + t + 4];
            }
            uint32_t bh[4][2], bl[4][2];
#pragma unroll
            for (int nt = 0; nt < 4; nt++) {
                int c0 = wc * 32 + nt * 8;
                bh[nt][0] = Bh[kb + t][c0 + g];
                bh[nt][1] = Bh[kb + t + 4][c0 + g];
                bl[nt][0] = Bl[kb + t][c0 + g];
                bl[nt][1] = Bl[kb + t + 4][c0 + g];
            }
#pragma unroll
            for (int mt = 0; mt < 4; mt++)
#pragma unroll
                for (int nt = 0; nt < 4; nt++) {
                    MMA_TF32(acc[mt][nt], ah[mt], bh[nt]);
                    MMA_TF32(acc[mt][nt], ah[mt], bl[nt]);
                    MMA_TF32(acc[mt][nt], al[mt], bh[nt]);
                }
        }
    }

    // Epilogue -> fp16
#pragma unroll
    for (int mt = 0; mt < 4; mt++) {
        int ra = row0 + wr * 64 + mt * 16 + g;
        int rb = ra + 8;
#pragma unroll
        for (int nt = 0; nt < 4; nt++) {
            int col = wc * 32 + nt * 8 + 2 * t;
            if (ra < N_NODES) {
                __half2 h = __floats2half2_rn(acc[mt][nt][0], acc[mt][nt][1]);
                *(__half2*)&g_xsh[(size_t)ra * DIM + col] = h;
            }
            if (rb < N_NODES) {
                __half2 h = __floats2half2_rn(acc[mt][nt][2], acc[mt][nt][3]);
                *(__half2*)&g_xsh[(size_t)rb * DIM + col] = h;
            }
        }
    }
}

// ================= aggregate: warp per node, 4-deep pipelined ================
// out[n] = dis[n] * (dis[n]*xp[n] + sum_{s in row n} dis[s]*xp[s])

__device__ __forceinline__ void acc_row(float4& acc, uint2 v, float w) {
    __half2 h01 = *(__half2*)&v.x;
    __half2 h23 = *(__half2*)&v.y;
    float2 f01 = __half22float2(h01);
    float2 f23 = __half22float2(h23);
    acc.x = fmaf(f01.x, w, acc.x);
    acc.y = fmaf(f01.y, w, acc.y);
    acc.z = fmaf(f23.x, w, acc.z);
    acc.w = fmaf(f23.y, w, acc.w);
}

__global__ void __launch_bounds__(256) k_agg(float* __restrict__ out) {
    int n = (blockIdx.x * blockDim.x + threadIdx.x) >> 5;
    int lane = threadIdx.x & 31;
    if (n >= N_NODES) return;

    int e   = g_start[n];
    int cnt = g_cursor[n] - e;
    float dn = g_dis[n];

    const uint2* xs = (const uint2*)g_xsh;  // 8B per lane per row

    float4 acc0 = make_float4(0.f, 0.f, 0.f, 0.f);
    float4 acc1 = make_float4(0.f, 0.f, 0.f, 0.f);
    float4 acc2 = make_float4(0.f, 0.f, 0.f, 0.f);
    float4 acc3 = make_float4(0.f, 0.f, 0.f, 0.f);
    acc_row(acc0, xs[(size_t)n * 32 + lane], dn);  // self loop

    // 4-deep software pipeline on the (broadcast) csr indices: while batch i
    // gathers, batch i+1's indices are loading.
    int i0 = (cnt > 0) ? g_csr[e + 0] : 0;
    int i1 = (cnt > 1) ? g_csr[e + 1] : 0;
    int i2 = (cnt > 2) ? g_csr[e + 2] : 0;
    int i3 = (cnt > 3) ? g_csr[e + 3] : 0;

    while (cnt >= 4) {
        int rem = cnt - 4;
        int j0 = (rem > 0) ? g_csr[e + 4] : 0;
        int j1 = (rem > 1) ? g_csr[e + 5] : 0;
        int j2 = (rem > 2) ? g_csr[e + 6] : 0;
        int j3 = (rem > 3) ? g_csr[e + 7] : 0;

        float w0 = g_dis[i0], w1 = g_dis[i1];
        float w2 = g_dis[i2], w3 = g_dis[i3];
        uint2 v0 = xs[(size_t)i0 * 32 + lane];
        uint2 v1 = xs[(size_t)i1 * 32 + lane];
        uint2 v2 = xs[(size_t)i2 * 32 + lane];
        uint2 v3 = xs[(size_t)i3 * 32 + lane];
        acc_row(acc0, v0, w0);
        acc_row(acc1, v1, w1);
        acc_row(acc2, v2, w2);
        acc_row(acc3, v3, w3);

        i0 = j0; i1 = j1; i2 = j2; i3 = j3;
        e += 4; cnt = rem;
    }
    if (cnt > 0) acc_row(acc0, xs[(size_t)i0 * 32 + lane], g_dis[i0]);
    if (cnt > 1) acc_row(acc1, xs[(size_t)i1 * 32 + lane], g_dis[i1]);
    if (cnt > 2) acc_row(acc2, xs[(size_t)i2 * 32 + lane], g_dis[i2]);

    float4 o;
    o.x = (acc0.x + acc1.x + acc2.x + acc3.x) * dn;
    o.y = (acc0.y + acc1.y + acc2.y + acc3.y) * dn;
    o.z = (acc0.z + acc1.z + acc2.z + acc3.z) * dn;
    o.w = (acc0.w + acc1.w + acc2.w + acc3.w) * dn;
    ((float4*)out)[(size_t)n * 32 + lane] = o;
}

// ================= side stream ctx =================

struct SideCtx {
    cudaStream_t s;
    cudaEvent_t ef, ej;
    bool ok;
    SideCtx() : s(0), ef(0), ej(0), ok(false) {
        if (cudaStreamCreateWithFlags(&s, cudaStreamNonBlocking) != cudaSuccess) return;
        if (cudaEventCreateWithFlags(&ef, cudaEventDisableTiming) != cudaSuccess) return;
        if (cudaEventCreateWithFlags(&ej, cudaEventDisableTiming) != cudaSuccess) return;
        ok = true;
    }
};
static SideCtx g_side;

// ================= launch =================

extern "C" void kernel_launch(void* const* d_in, const int* in_sizes, int n_in,
                              void* d_out, int out_size) {
    const float* x = 0;
    const float* W = 0;
    const void* ei = 0;
    for (int i = 0; i < n_in; i++) {
        if (in_sizes[i] == 2 * N_EDGES)        ei = d_in[i];
        else if (in_sizes[i] == DIM * DIM)     W  = (const float*)d_in[i];
        else if (in_sizes[i] == N_NODES * DIM) x  = (const float*)d_in[i];
    }
    float* out = (float*)d_out;

    int gemm_grid = (N_NODES + 127) / 128;
    bool forked = g_side.ok;

    if (forked) {
        cudaEventRecord(g_side.ef, 0);
        cudaStreamWaitEvent(g_side.s, g_side.ef, 0);
        k_gemm_mma<<<gemm_grid, 256, 0, g_side.s>>>(x, W);
        cudaEventRecord(g_side.ej, g_side.s);
    }

    k_init<<<(N_NODES + 255) / 256, 256>>>(ei);
    k_hist<<<(N_EDGES / 2 + 255) / 256, 256>>>(ei);
    k_scanA<<<NB_SCAN, 256>>>();
    k_scanB<<<1, 128>>>();
    k_scanC<<<NB_SCAN, 256>>>();
    k_fill<<<(N_EDGES / 2 + 255) / 256, 256>>>(ei);

    if (forked) {
        cudaStreamWaitEvent(0, g_side.ej, 0);
    } else {
        k_gemm_mma<<<gemm_grid, 256>>>(x, W);
    }

    long long total = (long long)N_NODES * 32;
    k_agg<<<(int)((total + 255) / 256), 256>>>(out);
}

// round 10
// speedup vs baseline: 1.3911x; 1.2147x over previous
#include <cuda_runtime.h>
#include <cuda_fp16.h>
#include <cstdint>

#define N_NODES 100000
#define N_EDGES 1600000
#define DIM 128
#define CAP 96   // per-node bucket capacity; P(deg > 96) ~ 1e-40 for Poisson(16)

// -------- device scratch (no cudaMalloc allowed) --------
__device__ int    g_is64;
__device__ int    g_degi[N_NODES];
__device__ int    g_bkt[(size_t)N_NODES * CAP];  // bucketed adjacency (src ids)
__device__ float  g_dis[N_NODES];
__device__ __half g_xsh[(size_t)N_NODES * DIM];  // x @ W, fp16

// ================= helpers =================

__device__ __forceinline__ uint32_t f2tf32_bits(float a) {
    uint32_t u;
    asm("cvt.rna.tf32.f32 %0, %1;" : "=r"(u) : "f"(a));
    return u;
}

#define MMA_TF32(d, a, b)                                                     \
    asm volatile("mma.sync.aligned.m16n8k8.row.col.f32.tf32.tf32.f32 "        \
                 "{%0,%1,%2,%3}, {%4,%5,%6,%7}, {%8,%9}, {%0,%1,%2,%3};"      \
                 : "+f"((d)[0]), "+f"((d)[1]), "+f"((d)[2]), "+f"((d)[3])     \
                 : "r"((a)[0]), "r"((a)[1]), "r"((a)[2]), "r"((a)[3]),        \
                   "r"((b)[0]), "r"((b)[1]))

// ================= init: zero degree + dtype detect =================

__global__ void k_init(const void* __restrict__ ei) {
    int i = blockIdx.x * blockDim.x + threadIdx.x;
    if (i < N_NODES) g_degi[i] = 0;
    if (blockIdx.x == 0) {
        const long long* p = (const long long*)ei;
        __shared__ int bad;
        if (threadIdx.x == 0) bad = 0;
        __syncthreads();
        for (int j = threadIdx.x; j < 2048; j += blockDim.x) {
            long long v = p[j];
            if (v < 0 || v >= N_NODES) bad = 1;
        }
        __syncthreads();
        if (threadIdx.x == 0) g_is64 = bad ? 0 : 1;
    }
}

// ================= bucket fill: histogram + adjacency in ONE pass ===========

__global__ void k_fillb(const void* __restrict__ ei) {
    int e2 = blockIdx.x * blockDim.x + threadIdx.x;
    if (e2 >= N_EDGES / 2) return;
    int s0, s1, d0, d1;
    if (g_is64) {
        const longlong2* p = (const longlong2*)ei;
        longlong2 s = p[e2];
        longlong2 d = p[N_EDGES / 2 + e2];
        s0 = (int)s.x; s1 = (int)s.y; d0 = (int)d.x; d1 = (int)d.y;
    } else {
        const int2* p = (const int2*)ei;
        int2 s = p[e2];
        int2 d = p[N_EDGES / 2 + e2];
        s0 = s.x; s1 = s.y; d0 = d.x; d1 = d.y;
    }
    int p0 = atomicAdd(&g_degi[d0], 1);
    if (p0 < CAP) g_bkt[(size_t)d0 * CAP + p0] = s0;
    int p1 = atomicAdd(&g_degi[d1], 1);
    if (p1 < CAP) g_bkt[(size_t)d1 * CAP + p1] = s1;
}

// ================= dis = rsqrt(deg + 1) =================

__global__ void k_dis() {
    int i = blockIdx.x * blockDim.x + threadIdx.x;
    if (i < N_NODES) g_dis[i] = rsqrtf((float)(g_degi[i] + 1));
}

// ================= GEMM via mma.sync tf32 (3-pass split), fp16 out ==========
// CTA: 128 rows x 128 cols, 256 threads (8 warps), warp tile 64x32.

#define KC 16
#define A_STR 20
#define B_STR 132

__global__ void __launch_bounds__(256) k_gemm_mma(const float* __restrict__ x,
                                                  const float* __restrict__ W) {
    __shared__ uint32_t Ah[128][A_STR];
    __shared__ uint32_t Al[128][A_STR];
    __shared__ uint32_t Bh[KC][B_STR];
    __shared__ uint32_t Bl[KC][B_STR];

    int tid = threadIdx.x;
    int wid = tid >> 5, lane = tid & 31;
    int g = lane >> 2, t = lane & 3;
    int wr = wid >> 2, wc = wid & 3;
    int row0 = blockIdx.x * 128;

    float acc[4][4][4];
#pragma unroll
    for (int mt = 0; mt < 4; mt++)
#pragma unroll
        for (int nt = 0; nt < 4; nt++)
#pragma unroll
            for (int q = 0; q < 4; q++) acc[mt][nt][q] = 0.f;

    for (int k0 = 0; k0 < 128; k0 += KC) {
        __syncthreads();
#pragma unroll
        for (int i = 0; i < 2; i++) {
            int idx = tid + i * 256;
            int r = idx >> 2, c4 = idx & 3;
            int gr = row0 + r;
            float4 v = make_float4(0.f, 0.f, 0.f, 0.f);
            if (gr < N_NODES) v = ((const float4*)x)[(size_t)gr * 32 + (k0 >> 2) + c4];
            uint32_t hx = f2tf32_bits(v.x), hy = f2tf32_bits(v.y);
            uint32_t hz = f2tf32_bits(v.z), hw = f2tf32_bits(v.w);
            Ah[r][c4 * 4 + 0] = hx; Ah[r][c4 * 4 + 1] = hy;
            Ah[r][c4 * 4 + 2] = hz; Ah[r][c4 * 4 + 3] = hw;
            Al[r][c4 * 4 + 0] = f2tf32_bits(v.x - __uint_as_float(hx));
            Al[r][c4 * 4 + 1] = f2tf32_bits(v.y - __uint_as_float(hy));
            Al[r][c4 * 4 + 2] = f2tf32_bits(v.z - __uint_as_float(hz));
            Al[r][c4 * 4 + 3] = f2tf32_bits(v.w - __uint_as_float(hw));
        }
#pragma unroll
        for (int i = 0; i < 2; i++) {
            int idx = tid + i * 256;
            int r = idx >> 5, c4 = idx & 31;
            float4 v = ((const float4*)W)[(size_t)(k0 + r) * 32 + c4];
            uint32_t hx = f2tf32_bits(v.x), hy = f2tf32_bits(v.y);
            uint32_t hz = f2tf32_bits(v.z), hw = f2tf32_bits(v.w);
            Bh[r][c4 * 4 + 0] = hx; Bh[r][c4 * 4 + 1] = hy;
            Bh[r][c4 * 4 + 2] = hz; Bh[r][c4 * 4 + 3] = hw;
            Bl[r][c4 * 4 + 0] = f2tf32_bits(v.x - __uint_as_float(hx));
            Bl[r][c4 * 4 + 1] = f2tf32_bits(v.y - __uint_as_float(hy));
            Bl[r][c4 * 4 + 2] = f2tf32_bits(v.z - __uint_as_float(hz));
            Bl[r][c4 * 4 + 3] = f2tf32_bits(v.w - __uint_as_float(hw));
        }
        __syncthreads();

#pragma unroll
        for (int kt = 0; kt < KC / 8; kt++) {
            int kb = kt * 8;
            uint32_t ah[4][4], al[4][4];
#pragma unroll
            for (int mt = 0; mt < 4; mt++) {
                int r0 = wr * 64 + mt * 16;
                ah[mt][0] = Ah[r0 + g][kb + t];
                ah[mt][1] = Ah[r0 + g + 8][kb + t];
                ah[mt][2] = Ah[r0 + g][kb + t + 4];
                ah[mt][3] = Ah[r0 + g + 8][kb + t + 4];
                al[mt][0] = Al[r0 + g][kb + t];
                al[mt][1] = Al[r0 + g + 8][kb + t];
                al[mt][2] = Al[r0 + g][kb + t + 4];
                al[mt][3] = Al[r0 + g + 8][kb + t + 4];
            }
            uint32_t bh[4][2], bl[4][2];
#pragma unroll
            for (int nt = 0; nt < 4; nt++) {
                int c0 = wc * 32 + nt * 8;
                bh[nt][0] = Bh[kb + t][c0 + g];
                bh[nt][1] = Bh[kb + t + 4][c0 + g];
                bl[nt][0] = Bl[kb + t][c0 + g];
                bl[nt][1] = Bl[kb + t + 4][c0 + g];
            }
#pragma unroll
            for (int mt = 0; mt < 4; mt++)
#pragma unroll
                for (int nt = 0; nt < 4; nt++) {
                    MMA_TF32(acc[mt][nt], ah[mt], bh[nt]);
                    MMA_TF32(acc[mt][nt], ah[mt], bl[nt]);
                    MMA_TF32(acc[mt][nt], al[mt], bh[nt]);
                }
        }
    }

    // Epilogue -> fp16
#pragma unroll
    for (int mt = 0; mt < 4; mt++) {
        int ra = row0 + wr * 64 + mt * 16 + g;
        int rb = ra + 8;
#pragma unroll
        for (int nt = 0; nt < 4; nt++) {
            int col = wc * 32 + nt * 8 + 2 * t;
            if (ra < N_NODES) {
                __half2 h = __floats2half2_rn(acc[mt][nt][0], acc[mt][nt][1]);
                *(__half2*)&g_xsh[(size_t)ra * DIM + col] = h;
            }
            if (rb < N_NODES) {
                __half2 h = __floats2half2_rn(acc[mt][nt][2], acc[mt][nt][3]);
                *(__half2*)&g_xsh[(size_t)rb * DIM + col] = h;
            }
        }
    }
}

// ================= aggregate: warp per node (exact R7 loop) ==================
// out[n] = dis[n] * (dis[n]*xp[n] + sum_{s in bucket n} dis[s]*xp[s])

__device__ __forceinline__ void acc_row(float4& acc, uint32_t lo, uint32_t hi,
                                        float w) {
    __half2 h01 = *(__half2*)&lo;
    __half2 h23 = *(__half2*)&hi;
    float2 f01 = __half22float2(h01);
    float2 f23 = __half22float2(h23);
    acc.x = fmaf(f01.x, w, acc.x);
    acc.y = fmaf(f01.y, w, acc.y);
    acc.z = fmaf(f23.x, w, acc.z);
    acc.w = fmaf(f23.y, w, acc.w);
}

__global__ void __launch_bounds__(256) k_agg(float* __restrict__ out) {
    int n = (blockIdx.x * blockDim.x + threadIdx.x) >> 5;
    int lane = threadIdx.x & 31;
    if (n >= N_NODES) return;

    int cnt = g_degi[n];
    if (cnt > CAP) cnt = CAP;
    float dn = g_dis[n];
    const int* bkt = &g_bkt[(size_t)n * CAP];

    const uint2* xs = (const uint2*)g_xsh;  // 8B per lane per row

    float4 acc0 = make_float4(0.f, 0.f, 0.f, 0.f);
    float4 acc1 = make_float4(0.f, 0.f, 0.f, 0.f);
    {
        uint2 v = xs[(size_t)n * 32 + lane];
        acc_row(acc0, v.x, v.y, dn);  // self loop weight dis[n]
    }

    int e = 0;
    while (e + 1 < cnt) {
        int s0 = bkt[e];
        int s1 = bkt[e + 1];
        float w0 = g_dis[s0];
        float w1 = g_dis[s1];
        uint2 v0 = xs[(size_t)s0 * 32 + lane];
        uint2 v1 = xs[(size_t)s1 * 32 + lane];
        acc_row(acc0, v0.x, v0.y, w0);
        acc_row(acc1, v1.x, v1.y, w1);
        e += 2;
    }
    if (e < cnt) {
        int s0 = bkt[e];
        float w0 = g_dis[s0];
        uint2 v0 = xs[(size_t)s0 * 32 + lane];
        acc_row(acc0, v0.x, v0.y, w0);
    }

    float4 acc;
    acc.x = (acc0.x + acc1.x) * dn;
    acc.y = (acc0.y + acc1.y) * dn;
    acc.z = (acc0.z + acc1.z) * dn;
    acc.w = (acc0.w + acc1.w) * dn;
    ((float4*)out)[(size_t)n * 32 + lane] = acc;
}

// ================= side stream ctx =================

struct SideCtx {
    cudaStream_t s;
    cudaEvent_t ef, ej;
    bool ok;
    SideCtx() : s(0), ef(0), ej(0), ok(false) {
        if (cudaStreamCreateWithFlags(&s, cudaStreamNonBlocking) != cudaSuccess) return;
        if (cudaEventCreateWithFlags(&ef, cudaEventDisableTiming) != cudaSuccess) return;
        if (cudaEventCreateWithFlags(&ej, cudaEventDisableTiming) != cudaSuccess) return;
        ok = true;
    }
};
static SideCtx g_side;

// ================= launch =================

extern "C" void kernel_launch(void* const* d_in, const int* in_sizes, int n_in,
                              void* d_out, int out_size) {
    const float* x = 0;
    const float* W = 0;
    const void* ei = 0;
    for (int i = 0; i < n_in; i++) {
        if (in_sizes[i] == 2 * N_EDGES)        ei = d_in[i];
        else if (in_sizes[i] == DIM * DIM)     W  = (const float*)d_in[i];
        else if (in_sizes[i] == N_NODES * DIM) x  = (const float*)d_in[i];
    }
    float* out = (float*)d_out;

    int gemm_grid = (N_NODES + 127) / 128;
    bool forked = g_side.ok;

    if (forked) {
        cudaEventRecord(g_side.ef, 0);
        cudaStreamWaitEvent(g_side.s, g_side.ef, 0);
        k_gemm_mma<<<gemm_grid, 256, 0, g_side.s>>>(x, W);
        cudaEventRecord(g_side.ej, g_side.s);
    }

    k_init<<<(N_NODES + 255) / 256, 256>>>(ei);
    k_fillb<<<(N_EDGES / 2 + 255) / 256, 256>>>(ei);
    k_dis<<<(N_NODES + 255) / 256, 256>>>();

    if (forked) {
        cudaStreamWaitEvent(0, g_side.ej, 0);
    } else {
        k_gemm_mma<<<gemm_grid, 256>>>(x, W);
    }

    long long total = (long long)N_NODES * 32;
    k_agg<<<(int)((total + 255) / 256), 256>>>(out);
}

// round 11
// speedup vs baseline: 1.6597x; 1.1931x over previous
#include <cuda_runtime.h>
#include <cuda_fp16.h>
#include <cuda_bf16.h>
#include <cstdint>

#define N_NODES 100000
#define N_EDGES 1600000
#define DIM 128
#define CAP 96   // per-node bucket capacity; P(deg > 96) ~ 1e-40 for Poisson(16)

// -------- device scratch (no cudaMalloc allowed) --------
__device__ int    g_is64;
__device__ int    g_degi[N_NODES];
__device__ int    g_bkt[(size_t)N_NODES * CAP];  // bucketed adjacency (src ids)
__device__ float  g_dis[N_NODES];
__device__ __half g_xsh[(size_t)N_NODES * DIM];  // x @ W, fp16

// ================= helpers =================

__device__ __forceinline__ uint32_t pack_bf2(__nv_bfloat16 a, __nv_bfloat16 b) {
    __nv_bfloat162 p(a, b);  // .x = first k (low half)
    return *(uint32_t*)&p;
}

// d += a * b  (m16n8k16, bf16 inputs packed as bf16x2 regs, fp32 accum)
#define MMA_BF16(d, a, b)                                                     \
    asm volatile("mma.sync.aligned.m16n8k16.row.col.f32.bf16.bf16.f32 "       \
                 "{%0,%1,%2,%3}, {%4,%5,%6,%7}, {%8,%9}, {%0,%1,%2,%3};"      \
                 : "+f"((d)[0]), "+f"((d)[1]), "+f"((d)[2]), "+f"((d)[3])     \
                 : "r"((a)[0]), "r"((a)[1]), "r"((a)[2]), "r"((a)[3]),        \
                   "r"((b)[0]), "r"((b)[1]))

// ================= init: zero degree + dtype detect =================

__global__ void k_init(const void* __restrict__ ei) {
    int i = blockIdx.x * blockDim.x + threadIdx.x;
    if (i < N_NODES) g_degi[i] = 0;
    if (blockIdx.x == 0) {
        const long long* p = (const long long*)ei;
        __shared__ int bad;
        if (threadIdx.x == 0) bad = 0;
        __syncthreads();
        for (int j = threadIdx.x; j < 2048; j += blockDim.x) {
            long long v = p[j];
            if (v < 0 || v >= N_NODES) bad = 1;
        }
        __syncthreads();
        if (threadIdx.x == 0) g_is64 = bad ? 0 : 1;
    }
}

// ================= bucket fill: histogram + adjacency in ONE pass ===========

__global__ void k_fillb(const void* __restrict__ ei) {
    int e2 = blockIdx.x * blockDim.x + threadIdx.x;
    if (e2 >= N_EDGES / 2) return;
    int s0, s1, d0, d1;
    if (g_is64) {
        const longlong2* p = (const longlong2*)ei;
        longlong2 s = p[e2];
        longlong2 d = p[N_EDGES / 2 + e2];
        s0 = (int)s.x; s1 = (int)s.y; d0 = (int)d.x; d1 = (int)d.y;
    } else {
        const int2* p = (const int2*)ei;
        int2 s = p[e2];
        int2 d = p[N_EDGES / 2 + e2];
        s0 = s.x; s1 = s.y; d0 = d.x; d1 = d.y;
    }
    int p0 = atomicAdd(&g_degi[d0], 1);
    if (p0 < CAP) g_bkt[(size_t)d0 * CAP + p0] = s0;
    int p1 = atomicAdd(&g_degi[d1], 1);
    if (p1 < CAP) g_bkt[(size_t)d1 * CAP + p1] = s1;
}

// ================= dis = rsqrt(deg + 1) =================

__global__ void k_dis() {
    int i = blockIdx.x * blockDim.x + threadIdx.x;
    if (i < N_NODES) g_dis[i] = rsqrtf((float)(g_degi[i] + 1));
}

// ================= GEMM via mma.sync bf16 m16n8k16 (2-term split) ===========
// CTA: 128 rows x 128 cols, 256 threads (8 warps), warp tile 64x32.
// K chunked by 32 (16 bf16x2 k-pairs) through smem. fp32 accum, fp16 out.
// 3 passes: hi*hi + hi*lo + lo*hi (lo*lo ~ 2^-18, dropped).

#define KCB 32          // k per chunk (floats)
#define KPC 16          // bf16x2 k-pairs per chunk
#define AB_STR 20       // A smem row stride in uint32: banks 20g+t distinct
#define BB_STR 132      // B smem row stride in uint32

__global__ void __launch_bounds__(256) k_gemm_mma(const float* __restrict__ x,
                                                  const float* __restrict__ W) {
    __shared__ uint32_t Ah[128][AB_STR];   // [row][kp]
    __shared__ uint32_t Al[128][AB_STR];
    __shared__ uint32_t Bh[KPC][BB_STR];   // [kp][n]
    __shared__ uint32_t Bl[KPC][BB_STR];

    int tid = threadIdx.x;
    int wid = tid >> 5, lane = tid & 31;
    int g = lane >> 2, t = lane & 3;
    int wr = wid >> 2, wc = wid & 3;
    int row0 = blockIdx.x * 128;

    float acc[4][4][4];
#pragma unroll
    for (int mt = 0; mt < 4; mt++)
#pragma unroll
        for (int nt = 0; nt < 4; nt++)
#pragma unroll
            for (int q = 0; q < 4; q++) acc[mt][nt][q] = 0.f;

    for (int k0 = 0; k0 < 128; k0 += KCB) {
        __syncthreads();
        // A chunk: 128 rows x 32 k = 1024 float4, 4 per thread.
        // float4 at (r, c) covers k = 4c..4c+3 -> kp 2c, 2c+1.
#pragma unroll
        for (int i = 0; i < 4; i++) {
            int idx = tid + i * 256;
            int r = idx >> 3, c = idx & 7;
            int gr = row0 + r;
            float4 v = make_float4(0.f, 0.f, 0.f, 0.f);
            if (gr < N_NODES) v = ((const float4*)x)[(size_t)gr * 32 + (k0 >> 2) + c];
            __nv_bfloat16 hx = __float2bfloat16_rn(v.x);
            __nv_bfloat16 hy = __float2bfloat16_rn(v.y);
            __nv_bfloat16 hz = __float2bfloat16_rn(v.z);
            __nv_bfloat16 hw = __float2bfloat16_rn(v.w);
            Ah[r][2 * c + 0] = pack_bf2(hx, hy);
            Ah[r][2 * c + 1] = pack_bf2(hz, hw);
            Al[r][2 * c + 0] = pack_bf2(
                __float2bfloat16_rn(v.x - __bfloat162float(hx)),
                __float2bfloat16_rn(v.y - __bfloat162float(hy)));
            Al[r][2 * c + 1] = pack_bf2(
                __float2bfloat16_rn(v.z - __bfloat162float(hz)),
                __float2bfloat16_rn(v.w - __bfloat162float(hw)));
        }
        // B chunk: pack k-pairs across adjacent W rows. 16 kp x 32 n-float4
        // groups = 512 groups, 2 per thread.
#pragma unroll
        for (int i = 0; i < 2; i++) {
            int idx = tid + i * 256;
            int kp = idx >> 5, n4 = idx & 31;
            float4 va = ((const float4*)W)[(size_t)(k0 + 2 * kp) * 32 + n4];
            float4 vb = ((const float4*)W)[(size_t)(k0 + 2 * kp + 1) * 32 + n4];
            const float* fa = (const float*)&va;
            const float* fb = (const float*)&vb;
#pragma unroll
            for (int j = 0; j < 4; j++) {
                __nv_bfloat16 ha = __float2bfloat16_rn(fa[j]);
                __nv_bfloat16 hb = __float2bfloat16_rn(fb[j]);
                Bh[kp][n4 * 4 + j] = pack_bf2(ha, hb);
                Bl[kp][n4 * 4 + j] = pack_bf2(
                    __float2bfloat16_rn(fa[j] - __bfloat162float(ha)),
                    __float2bfloat16_rn(fb[j] - __bfloat162float(hb)));
            }
        }
        __syncthreads();

#pragma unroll
        for (int kt = 0; kt < 2; kt++) {    // two k16 steps per 32-k chunk
            int kbp = kt * 8;               // kp base
            uint32_t ah[4][4], al[4][4];
#pragma unroll
            for (int mt = 0; mt < 4; mt++) {
                int r0 = wr * 64 + mt * 16;
                ah[mt][0] = Ah[r0 + g][kbp + t];
                ah[mt][1] = Ah[r0 + g + 8][kbp + t];
                ah[mt][2] = Ah[r0 + g][kbp + t + 4];
                ah[mt][3] = Ah[r0 + g + 8][kbp + t + 4];
                al[mt][0] = Al[r0 + g][kbp + t];
                al[mt][1] = Al[r0 + g + 8][kbp + t];
                al[mt][2] = Al[r0 + g][kbp + t + 4];
                al[mt][3] = Al[r0 + g + 8][kbp + t + 4];
            }
            uint32_t bh[4][2], bl[4][2];
#pragma unroll
            for (int nt = 0; nt < 4; nt++) {
                int c0 = wc * 32 + nt * 8;
                bh[nt][0] = Bh[kbp + t][c0 + g];
                bh[nt][1] = Bh[kbp + t + 4][c0 + g];
                bl[nt][0] = Bl[kbp + t][c0 + g];
                bl[nt][1] = Bl[kbp + t + 4][c0 + g];
            }
#pragma unroll
            for (int mt = 0; mt < 4; mt++)
#pragma unroll
                for (int nt = 0; nt < 4; nt++) {
                    MMA_BF16(acc[mt][nt], ah[mt], bh[nt]);
                    MMA_BF16(acc[mt][nt], ah[mt], bl[nt]);
                    MMA_BF16(acc[mt][nt], al[mt], bh[nt]);
                }
        }
    }

    // Epilogue -> fp16 (same acc layout as m16n8k8: c0,c1 -> row g col 2t,2t+1)
#pragma unroll
    for (int mt = 0; mt < 4; mt++) {
        int ra = row0 + wr * 64 + mt * 16 + g;
        int rb = ra + 8;
#pragma unroll
        for (int nt = 0; nt < 4; nt++) {
            int col = wc * 32 + nt * 8 + 2 * t;
            if (ra < N_NODES) {
                __half2 h = __floats2half2_rn(acc[mt][nt][0], acc[mt][nt][1]);
                *(__half2*)&g_xsh[(size_t)ra * DIM + col] = h;
            }
            if (rb < N_NODES) {
                __half2 h = __floats2half2_rn(acc[mt][nt][2], acc[mt][nt][3]);
                *(__half2*)&g_xsh[(size_t)rb * DIM + col] = h;
            }
        }
    }
}

// ================= aggregate: warp per node (exact R7/R10 loop) ==============
// out[n] = dis[n] * (dis[n]*xp[n] + sum_{s in bucket n} dis[s]*xp[s])

__device__ __forceinline__ void acc_row(float4& acc, uint32_t lo, uint32_t hi,
                                        float w) {
    __half2 h01 = *(__half2*)&lo;
    __half2 h23 = *(__half2*)&hi;
    float2 f01 = __half22float2(h01);
    float2 f23 = __half22float2(h23);
    acc.x = fmaf(f01.x, w, acc.x);
    acc.y = fmaf(f01.y, w, acc.y);
    acc.z = fmaf(f23.x, w, acc.z);
    acc.w = fmaf(f23.y, w, acc.w);
}

__global__ void __launch_bounds__(256) k_agg(float* __restrict__ out) {
    int n = (blockIdx.x * blockDim.x + threadIdx.x) >> 5;
    int lane = threadIdx.x & 31;
    if (n >= N_NODES) return;

    int cnt = g_degi[n];
    if (cnt > CAP) cnt = CAP;
    float dn = g_dis[n];
    const int* bkt = &g_bkt[(size_t)n * CAP];

    const uint2* xs = (const uint2*)g_xsh;

    float4 acc0 = make_float4(0.f, 0.f, 0.f, 0.f);
    float4 acc1 = make_float4(0.f, 0.f, 0.f, 0.f);
    {
        uint2 v = xs[(size_t)n * 32 + lane];
        acc_row(acc0, v.x, v.y, dn);  // self loop weight dis[n]
    }

    int e = 0;
    while (e + 1 < cnt) {
        int s0 = bkt[e];
        int s1 = bkt[e + 1];
        float w0 = g_dis[s0];
        float w1 = g_dis[s1];
        uint2 v0 = xs[(size_t)s0 * 32 + lane];
        uint2 v1 = xs[(size_t)s1 * 32 + lane];
        acc_row(acc0, v0.x, v0.y, w0);
        acc_row(acc1, v1.x, v1.y, w1);
        e += 2;
    }
    if (e < cnt) {
        int s0 = bkt[e];
        float w0 = g_dis[s0];
        uint2 v0 = xs[(size_t)s0 * 32 + lane];
        acc_row(acc0, v0.x, v0.y, w0);
    }

    float4 acc;
    acc.x = (acc0.x + acc1.x) * dn;
    acc.y = (acc0.y + acc1.y) * dn;
    acc.z = (acc0.z + acc1.z) * dn;
    acc.w = (acc0.w + acc1.w) * dn;
    ((float4*)out)[(size_t)n * 32 + lane] = acc;
}

// ================= side stream ctx =================

struct SideCtx {
    cudaStream_t s;
    cudaEvent_t ef, ej;
    bool ok;
    SideCtx() : s(0), ef(0), ej(0), ok(false) {
        if (cudaStreamCreateWithFlags(&s, cudaStreamNonBlocking) != cudaSuccess) return;
        if (cudaEventCreateWithFlags(&ef, cudaEventDisableTiming) != cudaSuccess) return;
        if (cudaEventCreateWithFlags(&ej, cudaEventDisableTiming) != cudaSuccess) return;
        ok = true;
    }
};
static SideCtx g_side;

// ================= launch =================

extern "C" void kernel_launch(void* const* d_in, const int* in_sizes, int n_in,
                              void* d_out, int out_size) {
    const float* x = 0;
    const float* W = 0;
    const void* ei = 0;
    for (int i = 0; i < n_in; i++) {
        if (in_sizes[i] == 2 * N_EDGES)        ei = d_in[i];
        else if (in_sizes[i] == DIM * DIM)     W  = (const float*)d_in[i];
        else if (in_sizes[i] == N_NODES * DIM) x  = (const float*)d_in[i];
    }
    float* out = (float*)d_out;

    int gemm_grid = (N_NODES + 127) / 128;
    bool forked = g_side.ok;

    if (forked) {
        cudaEventRecord(g_side.ef, 0);
        cudaStreamWaitEvent(g_side.s, g_side.ef, 0);
        k_gemm_mma<<<gemm_grid, 256, 0, g_side.s>>>(x, W);
        cudaEventRecord(g_side.ej, g_side.s);
    }

    k_init<<<(N_NODES + 255) / 256, 256>>>(ei);
    k_fillb<<<(N_EDGES / 2 + 255) / 256, 256>>>(ei);
    k_dis<<<(N_NODES + 255) / 256, 256>>>();

    if (forked) {
        cudaStreamWaitEvent(0, g_side.ej, 0);
    } else {
        k_gemm_mma<<<gemm_grid, 256>>>(x, W);
    }

    long long total = (long long)N_NODES * 32;
    k_agg<<<(int)((total + 255) / 256), 256>>>(out);
}